// round 6
// baseline (speedup 1.0000x reference)
#include <cuda_runtime.h>
#include <cuda_fp16.h>
#include <cstdint>
#include <cstddef>

#define N_NODES 100000
#define B_BATCH 20000
#define K_NBR   10
#define F_DIM   256
#define H_DIM   128

// ---------------------------------------------------------------------------
// Device scratch
// ---------------------------------------------------------------------------
__device__ float g_table[(size_t)N_NODES * 384];      // [q|k|v] per node
// Prepacked fp16 B fragments (mma.m16n8k16 register layout), hi/lo split.
__device__ uint2 g_Ba[3 * 16 * 2 * 512];
__device__ uint2 g_Bb[3 *  8 * 2 * 512];

// ---------------------------------------------------------------------------
// Helpers
// ---------------------------------------------------------------------------
__device__ __forceinline__ uint32_t smem_u32(const void* p) {
    uint32_t a;
    asm("{ .reg .u64 t; cvta.to.shared.u64 t, %1; cvt.u32.u64 %0, t; }"
        : "=r"(a) : "l"(p));
    return a;
}
__device__ __forceinline__ uint32_t pack_f16x2(float a, float b) {
    half2 h = __floats2half2_rn(a, b);
    return *(uint32_t*)&h;
}
__device__ __forceinline__ float f16_round(float x) {
    return __half2float(__float2half_rn(x));
}
__device__ __forceinline__ float tanh_fast(float x) {
    float e = __expf(2.f * x);
    return 1.f - __fdividef(2.f, e + 1.f);
}
__device__ __forceinline__ void ldm4(uint32_t* r, uint32_t addr) {
    asm volatile("ldmatrix.sync.aligned.m8n8.x4.shared.b16 {%0,%1,%2,%3}, [%4];"
                 : "=r"(r[0]), "=r"(r[1]), "=r"(r[2]), "=r"(r[3]) : "r"(addr));
}
__device__ __forceinline__ void mma16816(float* d, const uint32_t* a,
                                         uint32_t b0, uint32_t b1) {
    asm volatile(
        "mma.sync.aligned.m16n8k16.row.col.f32.f16.f16.f32 "
        "{%0,%1,%2,%3}, {%4,%5,%6,%7}, {%8,%9}, {%0,%1,%2,%3};"
        : "+f"(d[0]), "+f"(d[1]), "+f"(d[2]), "+f"(d[3])
        : "r"(a[0]), "r"(a[1]), "r"(a[2]), "r"(a[3]), "r"(b0), "r"(b1));
}

// ---------------------------------------------------------------------------
// Kernel 0: prepack weights into mma B-fragment layout, fp16 hi + lo split.
// ---------------------------------------------------------------------------
__global__ void prep_weights_kernel(
    const float* __restrict__ W1a, const float* __restrict__ W1b,
    const float* __restrict__ W2a, const float* __restrict__ W2b,
    const float* __restrict__ W3a, const float* __restrict__ W3b)
{
    const float* Wa[3] = {W1a, W2a, W3a};
    const float* Wb[3] = {W1b, W2b, W3b};
    int i = blockIdx.x * blockDim.x + threadIdx.x;   // 36864 threads
    const float* W;
    uint2 *dst_hi, *dst_lo;
    int lane, nt, ks;
    if (i < 24576) {                                 // Ba: 3*16*16*32
        lane = i & 31; nt = (i >> 5) & 15; ks = (i >> 9) & 15;
        int p = i >> 13;
        W = Wa[p];
        size_t base = (size_t)((p * 16 + ks) * 2) * 512 + nt * 32 + lane;
        dst_hi = g_Ba + base;
        dst_lo = g_Ba + base + 512;
    } else {                                         // Bb: 3*8*16*32
        int ib = i - 24576;
        lane = ib & 31; nt = (ib >> 5) & 15; ks = (ib >> 9) & 7;
        int p = ib >> 12;
        W = Wb[p];
        size_t base = (size_t)((p * 8 + ks) * 2) * 512 + nt * 32 + lane;
        dst_hi = g_Bb + base;
        dst_lo = g_Bb + base + 512;
    }
    int k = ks * 16 + (lane & 3) * 2;
    int n = nt * 8 + (lane >> 2);
    float w00 = W[(size_t)k * H_DIM + n];
    float w01 = W[(size_t)(k + 1) * H_DIM + n];
    float w10 = W[(size_t)(k + 8) * H_DIM + n];
    float w11 = W[(size_t)(k + 9) * H_DIM + n];
    float h00 = f16_round(w00), h01 = f16_round(w01);
    float h10 = f16_round(w10), h11 = f16_round(w11);
    uint2 hi, lo;
    hi.x = pack_f16x2(h00, h01);
    hi.y = pack_f16x2(h10, h11);
    lo.x = pack_f16x2(w00 - h00, w01 - h01);
    lo.y = pack_f16x2(w10 - h10, w11 - h11);
    *dst_hi = hi;
    *dst_lo = lo;
}

// ---------------------------------------------------------------------------
// Kernel 1: HMMA precompute (unchanged from round 5).
// CTA = 128x128 tile, 8 warps as 2m x 4n, warp tile 64x32.
// Split-2 on B: D = A16 * (Bh + Bl), fp32 accum. 102.4 KB smem -> 2 CTAs/SM.
// ---------------------------------------------------------------------------
#define XSTR 264
#define HSTR 136
#define X_OFF 0u
#define H_OFF 67584u                     // 128*264*2
#define PC_SMEM 102400u

__global__ void __launch_bounds__(256, 2) precompute_mma_kernel(
    const float* __restrict__ embed)
{
    extern __shared__ unsigned char smem[];
    const uint32_t sbase = smem_u32(smem);
    const int tid  = threadIdx.x;
    const int wid  = tid >> 5;
    const int lane = tid & 31;
    const int wm   = wid & 1;
    const int wn   = wid >> 1;
    const long brow = (long)blockIdx.x * 128;

    const uint32_t loffX = (uint32_t)((lane & 15) * XSTR + (lane >> 4) * 8) * 2;
    const uint32_t loffH = (uint32_t)((lane & 15) * HSTR + (lane >> 4) * 8) * 2;

    for (int i = tid; i < 128 * 64; i += 256) {
        int r  = i >> 6;
        int c4 = i & 63;
        long grow = brow + r;
        float4 v = make_float4(0.f, 0.f, 0.f, 0.f);
        if (grow < N_NODES) v = *(const float4*)(embed + grow * F_DIM + c4 * 4);
        uint32_t off = ((uint32_t)r * XSTR + c4 * 4) * 2;
        *(uint32_t*)(smem + X_OFF + off)     = pack_f16x2(v.x, v.y);
        *(uint32_t*)(smem + X_OFF + off + 4) = pack_f16x2(v.z, v.w);
    }
    __syncthreads();

    const int rbase = (lane >> 2);
    const int cbase = (lane & 3) * 2;

    for (int p = 0; p < 3; p++) {
        float acc[4][4][4];
        #pragma unroll
        for (int mt = 0; mt < 4; mt++)
            #pragma unroll
            for (int nt = 0; nt < 4; nt++)
                #pragma unroll
                for (int c = 0; c < 4; c++) acc[mt][nt][c] = 0.f;

        for (int ks = 0; ks < 16; ks++) {
            uint32_t a[4][4];
            uint32_t kb = (uint32_t)ks * 32;
            #pragma unroll
            for (int mt = 0; mt < 4; mt++) {
                uint32_t ro = (uint32_t)(wm * 64 + mt * 16) * XSTR * 2;
                ldm4(a[mt], sbase + X_OFF + ro + kb + loffX);
            }
            const uint2* pb = g_Ba + (size_t)((p * 16 + ks) * 2) * 512
                              + (wn * 4) * 32 + lane;
            uint2 bh[4], bl[4];
            #pragma unroll
            for (int j = 0; j < 4; j++) { bh[j] = pb[j * 32]; bl[j] = pb[512 + j * 32]; }
            #pragma unroll
            for (int j = 0; j < 4; j++) {
                #pragma unroll
                for (int mt = 0; mt < 4; mt++) {
                    mma16816(acc[mt][j], a[mt], bh[j].x, bh[j].y);
                    mma16816(acc[mt][j], a[mt], bl[j].x, bl[j].y);
                }
            }
        }

        #pragma unroll
        for (int mt = 0; mt < 4; mt++) {
            #pragma unroll
            for (int nt = 0; nt < 4; nt++) {
                int col = wn * 32 + nt * 8 + cbase;
                int r0  = wm * 64 + mt * 16 + rbase;
                float t0 = tanh_fast(acc[mt][nt][0]);
                float t1 = tanh_fast(acc[mt][nt][1]);
                float t2 = tanh_fast(acc[mt][nt][2]);
                float t3 = tanh_fast(acc[mt][nt][3]);
                uint32_t o0 = ((uint32_t)r0 * HSTR + col) * 2;
                uint32_t o1 = ((uint32_t)(r0 + 8) * HSTR + col) * 2;
                *(uint32_t*)(smem + H_OFF + o0) = pack_f16x2(t0, t1);
                *(uint32_t*)(smem + H_OFF + o1) = pack_f16x2(t2, t3);
            }
        }
        __syncthreads();

        #pragma unroll
        for (int mt = 0; mt < 4; mt++)
            #pragma unroll
            for (int nt = 0; nt < 4; nt++)
                #pragma unroll
                for (int c = 0; c < 4; c++) acc[mt][nt][c] = 0.f;

        for (int ks = 0; ks < 8; ks++) {
            uint32_t a[4][4];
            uint32_t kb = (uint32_t)ks * 32;
            #pragma unroll
            for (int mt = 0; mt < 4; mt++) {
                uint32_t ro = (uint32_t)(wm * 64 + mt * 16) * HSTR * 2;
                ldm4(a[mt], sbase + H_OFF + ro + kb + loffH);
            }
            const uint2* pb = g_Bb + (size_t)((p * 8 + ks) * 2) * 512
                              + (wn * 4) * 32 + lane;
            uint2 bh[4], bl[4];
            #pragma unroll
            for (int j = 0; j < 4; j++) { bh[j] = pb[j * 32]; bl[j] = pb[512 + j * 32]; }
            #pragma unroll
            for (int j = 0; j < 4; j++) {
                #pragma unroll
                for (int mt = 0; mt < 4; mt++) {
                    mma16816(acc[mt][j], a[mt], bh[j].x, bh[j].y);
                    mma16816(acc[mt][j], a[mt], bl[j].x, bl[j].y);
                }
            }
        }

        #pragma unroll
        for (int mt = 0; mt < 4; mt++) {
            #pragma unroll
            for (int nt = 0; nt < 4; nt++) {
                int col = wn * 32 + nt * 8 + cbase;
                long r0 = brow + wm * 64 + mt * 16 + rbase;
                if (r0 < N_NODES) {
                    float2 v = make_float2(acc[mt][nt][0], acc[mt][nt][1]);
                    *(float2*)(g_table + r0 * 384 + p * H_DIM + col) = v;
                }
                if (r0 + 8 < N_NODES) {
                    float2 v = make_float2(acc[mt][nt][2], acc[mt][nt][3]);
                    *(float2*)(g_table + (r0 + 8) * 384 + p * H_DIM + col) = v;
                }
            }
        }
        __syncthreads();
    }
}

// ---------------------------------------------------------------------------
// Kernel 2: warp-autonomous attention. One warp per batch, no shared memory.
// Lane l owns dims 4l..4l+3. Scores via shfl_xor butterflies; lane j keeps
// score column j; softmax row reductions via butterflies; v prefetched in
// registers; output via 10 lane broadcasts.
// ---------------------------------------------------------------------------
__global__ void __launch_bounds__(256) attention_kernel(
    const int* __restrict__ neighbors, float* __restrict__ out)
{
    const int b    = blockIdx.x * 8 + (threadIdx.x >> 5);
    const int lane = threadIdx.x & 31;

    int mynode = 0;
    if (lane < K_NBR) mynode = neighbors[(size_t)b * K_NBR + lane];

    int node[K_NBR];
    #pragma unroll
    for (int j = 0; j < K_NBR; j++)
        node[j] = __shfl_sync(0xffffffffu, mynode, j);

    const int d = lane * 4;

    // Gather q and k rows into registers (20 independent LDG.128)
    float4 qv[K_NBR], kv[K_NBR];
    #pragma unroll
    for (int j = 0; j < K_NBR; j++) {
        const float* base = g_table + (size_t)node[j] * 384;
        qv[j] = *(const float4*)(base + d);
        kv[j] = *(const float4*)(base + 128 + d);
    }

    // Score matrix: lane j retains s[i][j] in scol[i]
    float scol[K_NBR];
    #pragma unroll
    for (int i = 0; i < K_NBR; i++) {
        #pragma unroll
        for (int j = 0; j < K_NBR; j++) {
            float s = qv[i].x * kv[j].x;
            s = fmaf(qv[i].y, kv[j].y, s);
            s = fmaf(qv[i].z, kv[j].z, s);
            s = fmaf(qv[i].w, kv[j].w, s);
            s += __shfl_xor_sync(0xffffffffu, s, 16);
            s += __shfl_xor_sync(0xffffffffu, s, 8);
            s += __shfl_xor_sync(0xffffffffu, s, 4);
            s += __shfl_xor_sync(0xffffffffu, s, 2);
            s += __shfl_xor_sync(0xffffffffu, s, 1);
            if (lane == j) scol[i] = s;
        }
    }

    // Prefetch v rows (latency hidden under softmax)
    float4 vv[K_NBR];
    #pragma unroll
    for (int j = 0; j < K_NBR; j++)
        vv[j] = *(const float4*)(g_table + (size_t)node[j] * 384 + 256 + d);

    // Softmax + column weights: colw[j] = sum_i exp(s_ij - m_i) / rowsum_i
    float colw = 0.f;
    #pragma unroll
    for (int i = 0; i < K_NBR; i++) {
        float s = (lane < K_NBR) ? scol[i] : -1e30f;
        float m = s;
        m = fmaxf(m, __shfl_xor_sync(0xffffffffu, m, 16));
        m = fmaxf(m, __shfl_xor_sync(0xffffffffu, m, 8));
        m = fmaxf(m, __shfl_xor_sync(0xffffffffu, m, 4));
        m = fmaxf(m, __shfl_xor_sync(0xffffffffu, m, 2));
        m = fmaxf(m, __shfl_xor_sync(0xffffffffu, m, 1));
        float e = (lane < K_NBR) ? __expf(s - m) : 0.f;
        float sum = e;
        sum += __shfl_xor_sync(0xffffffffu, sum, 16);
        sum += __shfl_xor_sync(0xffffffffu, sum, 8);
        sum += __shfl_xor_sync(0xffffffffu, sum, 4);
        sum += __shfl_xor_sync(0xffffffffu, sum, 2);
        sum += __shfl_xor_sync(0xffffffffu, sum, 1);
        colw += e / sum;
    }

    // out[b, 4l..4l+3] = sum_j colw_j * v_j
    float4 o = make_float4(0.f, 0.f, 0.f, 0.f);
    #pragma unroll
    for (int j = 0; j < K_NBR; j++) {
        float cw = __shfl_sync(0xffffffffu, colw, j);
        o.x = fmaf(cw, vv[j].x, o.x);
        o.y = fmaf(cw, vv[j].y, o.y);
        o.z = fmaf(cw, vv[j].z, o.z);
        o.w = fmaf(cw, vv[j].w, o.w);
    }
    *(float4*)(out + (size_t)b * H_DIM + d) = o;
}

// ---------------------------------------------------------------------------
extern "C" void kernel_launch(void* const* d_in, const int* in_sizes, int n_in,
                              void* d_out, int out_size) {
    const int*   neighbors = (const int*)d_in[0];
    const float* embed     = (const float*)d_in[1];
    const float* W1a       = (const float*)d_in[2];
    const float* W1b       = (const float*)d_in[3];
    const float* W2a       = (const float*)d_in[4];
    const float* W2b       = (const float*)d_in[5];
    const float* W3a       = (const float*)d_in[6];
    const float* W3b       = (const float*)d_in[7];
    float* out = (float*)d_out;

    prep_weights_kernel<<<144, 256>>>(W1a, W1b, W2a, W2b, W3a, W3b);

    cudaFuncSetAttribute(precompute_mma_kernel,
                         cudaFuncAttributeMaxDynamicSharedMemorySize,
                         (int)PC_SMEM);
    const int grid1 = (N_NODES + 127) / 128;   // 782
    precompute_mma_kernel<<<grid1, 256, PC_SMEM>>>(embed);

    attention_kernel<<<B_BATCH / 8, 256>>>(neighbors, out);
}

// round 7
// speedup vs baseline: 1.2539x; 1.2539x over previous
#include <cuda_runtime.h>
#include <cuda_fp16.h>
#include <cstdint>
#include <cstddef>

#define N_NODES 100000
#define B_BATCH 20000
#define K_NBR   10
#define F_DIM   256
#define H_DIM   128

// ---------------------------------------------------------------------------
// Device scratch
// ---------------------------------------------------------------------------
__device__ float g_table[(size_t)N_NODES * 384];      // [q|k|v] per node
// Prepacked fp16 B fragments (mma.m16n8k16 register layout), single term.
// Ba: [p][kstep(16)][ntile(16)*32+lane]  (K=256 GEMM1)
// Bb: [p][kstep(8) ][ntile(16)*32+lane]  (K=128 GEMM2)
__device__ uint2 g_Ba[3 * 16 * 512];
__device__ uint2 g_Bb[3 *  8 * 512];

// ---------------------------------------------------------------------------
// Helpers
// ---------------------------------------------------------------------------
__device__ __forceinline__ uint32_t smem_u32(const void* p) {
    uint32_t a;
    asm("{ .reg .u64 t; cvta.to.shared.u64 t, %1; cvt.u32.u64 %0, t; }"
        : "=r"(a) : "l"(p));
    return a;
}
__device__ __forceinline__ uint32_t pack_f16x2(float a, float b) {
    half2 h = __floats2half2_rn(a, b);
    return *(uint32_t*)&h;
}
__device__ __forceinline__ float tanh_fast(float x) {
    float e = __expf(2.f * x);
    return 1.f - __fdividef(2.f, e + 1.f);
}
__device__ __forceinline__ void ldm4(uint32_t* r, uint32_t addr) {
    asm volatile("ldmatrix.sync.aligned.m8n8.x4.shared.b16 {%0,%1,%2,%3}, [%4];"
                 : "=r"(r[0]), "=r"(r[1]), "=r"(r[2]), "=r"(r[3]) : "r"(addr));
}
__device__ __forceinline__ void mma16816(float* d, const uint32_t* a,
                                         uint32_t b0, uint32_t b1) {
    asm volatile(
        "mma.sync.aligned.m16n8k16.row.col.f32.f16.f16.f32 "
        "{%0,%1,%2,%3}, {%4,%5,%6,%7}, {%8,%9}, {%0,%1,%2,%3};"
        : "+f"(d[0]), "+f"(d[1]), "+f"(d[2]), "+f"(d[3])
        : "r"(a[0]), "r"(a[1]), "r"(a[2]), "r"(a[3]), "r"(b0), "r"(b1));
}

// ---------------------------------------------------------------------------
// Kernel 0: prepack weights into mma B-fragment layout (fp16, single term).
//   reg.x: k = kstep*16 + (lane%4)*2 + {0,1}, n = ntile*8 + lane/4
//   reg.y: k = ... + 8 + {0,1}
// ---------------------------------------------------------------------------
__global__ void prep_weights_kernel(
    const float* __restrict__ W1a, const float* __restrict__ W1b,
    const float* __restrict__ W2a, const float* __restrict__ W2b,
    const float* __restrict__ W3a, const float* __restrict__ W3b)
{
    const float* Wa[3] = {W1a, W2a, W3a};
    const float* Wb[3] = {W1b, W2b, W3b};
    int i = blockIdx.x * blockDim.x + threadIdx.x;   // 36864 threads
    const float* W;
    uint2* dst;
    int lane, nt, ks;
    if (i < 24576) {                                 // Ba: 3*16*16*32
        lane = i & 31; nt = (i >> 5) & 15; ks = (i >> 9) & 15;
        int p = i >> 13;
        W = Wa[p];
        dst = g_Ba + (size_t)(p * 16 + ks) * 512 + nt * 32 + lane;
    } else {                                         // Bb: 3*8*16*32
        int ib = i - 24576;
        lane = ib & 31; nt = (ib >> 5) & 15; ks = (ib >> 9) & 7;
        int p = ib >> 12;
        W = Wb[p];
        dst = g_Bb + (size_t)(p * 8 + ks) * 512 + nt * 32 + lane;
    }
    int k = ks * 16 + (lane & 3) * 2;
    int n = nt * 8 + (lane >> 2);
    float w00 = W[(size_t)k * H_DIM + n];
    float w01 = W[(size_t)(k + 1) * H_DIM + n];
    float w10 = W[(size_t)(k + 8) * H_DIM + n];
    float w11 = W[(size_t)(k + 9) * H_DIM + n];
    uint2 fr;
    fr.x = pack_f16x2(w00, w01);
    fr.y = pack_f16x2(w10, w11);
    *dst = fr;
}

// ---------------------------------------------------------------------------
// Kernel 1: HMMA precompute. CTA = 128x128 tile, 8 warps as 2m x 4n,
// warp tile 64x32. Single-pass fp16: D = A16 * B16, fp32 accum.
// smem: X fp16 [128][264] + H fp16 [128][136] = 102.4 KB -> 2 CTAs/SM.
// ---------------------------------------------------------------------------
#define XSTR 264
#define HSTR 136
#define X_OFF 0u
#define H_OFF 67584u                     // 128*264*2
#define PC_SMEM 102400u

__global__ void __launch_bounds__(256, 2) precompute_mma_kernel(
    const float* __restrict__ embed)
{
    extern __shared__ unsigned char smem[];
    const uint32_t sbase = smem_u32(smem);
    const int tid  = threadIdx.x;
    const int wid  = tid >> 5;
    const int lane = tid & 31;
    const int wm   = wid & 1;
    const int wn   = wid >> 1;
    const long brow = (long)blockIdx.x * 128;

    const uint32_t loffX = (uint32_t)((lane & 15) * XSTR + (lane >> 4) * 8) * 2;
    const uint32_t loffH = (uint32_t)((lane & 15) * HSTR + (lane >> 4) * 8) * 2;

    for (int i = tid; i < 128 * 64; i += 256) {
        int r  = i >> 6;
        int c4 = i & 63;
        long grow = brow + r;
        float4 v = make_float4(0.f, 0.f, 0.f, 0.f);
        if (grow < N_NODES) v = *(const float4*)(embed + grow * F_DIM + c4 * 4);
        uint32_t off = ((uint32_t)r * XSTR + c4 * 4) * 2;
        *(uint32_t*)(smem + X_OFF + off)     = pack_f16x2(v.x, v.y);
        *(uint32_t*)(smem + X_OFF + off + 4) = pack_f16x2(v.z, v.w);
    }
    __syncthreads();

    const int rbase = (lane >> 2);
    const int cbase = (lane & 3) * 2;

    for (int p = 0; p < 3; p++) {
        float acc[4][4][4];
        #pragma unroll
        for (int mt = 0; mt < 4; mt++)
            #pragma unroll
            for (int nt = 0; nt < 4; nt++)
                #pragma unroll
                for (int c = 0; c < 4; c++) acc[mt][nt][c] = 0.f;

        // ================= GEMM1: X[128,256] @ Wa -> 128x128 =================
        for (int ks = 0; ks < 16; ks++) {
            uint32_t a[4][4];
            uint32_t kb = (uint32_t)ks * 32;
            #pragma unroll
            for (int mt = 0; mt < 4; mt++) {
                uint32_t ro = (uint32_t)(wm * 64 + mt * 16) * XSTR * 2;
                ldm4(a[mt], sbase + X_OFF + ro + kb + loffX);
            }
            const uint2* pb = g_Ba + (size_t)(p * 16 + ks) * 512
                              + (wn * 4) * 32 + lane;
            uint2 bf[4];
            #pragma unroll
            for (int j = 0; j < 4; j++) bf[j] = pb[j * 32];
            #pragma unroll
            for (int j = 0; j < 4; j++) {
                #pragma unroll
                for (int mt = 0; mt < 4; mt++)
                    mma16816(acc[mt][j], a[mt], bf[j].x, bf[j].y);
            }
        }

        // ---- Epilogue 1: tanh -> H smem (fp16) ----
        #pragma unroll
        for (int mt = 0; mt < 4; mt++) {
            #pragma unroll
            for (int nt = 0; nt < 4; nt++) {
                int col = wn * 32 + nt * 8 + cbase;
                int r0  = wm * 64 + mt * 16 + rbase;
                float t0 = tanh_fast(acc[mt][nt][0]);
                float t1 = tanh_fast(acc[mt][nt][1]);
                float t2 = tanh_fast(acc[mt][nt][2]);
                float t3 = tanh_fast(acc[mt][nt][3]);
                uint32_t o0 = ((uint32_t)r0 * HSTR + col) * 2;
                uint32_t o1 = ((uint32_t)(r0 + 8) * HSTR + col) * 2;
                *(uint32_t*)(smem + H_OFF + o0) = pack_f16x2(t0, t1);
                *(uint32_t*)(smem + H_OFF + o1) = pack_f16x2(t2, t3);
            }
        }
        __syncthreads();

        // ================= GEMM2: H[128,128] @ Wb -> 128x128 =================
        #pragma unroll
        for (int mt = 0; mt < 4; mt++)
            #pragma unroll
            for (int nt = 0; nt < 4; nt++)
                #pragma unroll
                for (int c = 0; c < 4; c++) acc[mt][nt][c] = 0.f;

        for (int ks = 0; ks < 8; ks++) {
            uint32_t a[4][4];
            uint32_t kb = (uint32_t)ks * 32;
            #pragma unroll
            for (int mt = 0; mt < 4; mt++) {
                uint32_t ro = (uint32_t)(wm * 64 + mt * 16) * HSTR * 2;
                ldm4(a[mt], sbase + H_OFF + ro + kb + loffH);
            }
            const uint2* pb = g_Bb + (size_t)(p * 8 + ks) * 512
                              + (wn * 4) * 32 + lane;
            uint2 bf[4];
            #pragma unroll
            for (int j = 0; j < 4; j++) bf[j] = pb[j * 32];
            #pragma unroll
            for (int j = 0; j < 4; j++) {
                #pragma unroll
                for (int mt = 0; mt < 4; mt++)
                    mma16816(acc[mt][j], a[mt], bf[j].x, bf[j].y);
            }
        }

        // ---- Epilogue 2: write to g_table ----
        #pragma unroll
        for (int mt = 0; mt < 4; mt++) {
            #pragma unroll
            for (int nt = 0; nt < 4; nt++) {
                int col = wn * 32 + nt * 8 + cbase;
                long r0 = brow + wm * 64 + mt * 16 + rbase;
                if (r0 < N_NODES) {
                    float2 v = make_float2(acc[mt][nt][0], acc[mt][nt][1]);
                    *(float2*)(g_table + r0 * 384 + p * H_DIM + col) = v;
                }
                if (r0 + 8 < N_NODES) {
                    float2 v = make_float2(acc[mt][nt][2], acc[mt][nt][3]);
                    *(float2*)(g_table + (r0 + 8) * 384 + p * H_DIM + col) = v;
                }
            }
        }
        __syncthreads();
    }
}

// ---------------------------------------------------------------------------
// Kernel 2: warp-autonomous attention (unchanged from round 6).
// ---------------------------------------------------------------------------
__global__ void __launch_bounds__(256) attention_kernel(
    const int* __restrict__ neighbors, float* __restrict__ out)
{
    const int b    = blockIdx.x * 8 + (threadIdx.x >> 5);
    const int lane = threadIdx.x & 31;

    int mynode = 0;
    if (lane < K_NBR) mynode = neighbors[(size_t)b * K_NBR + lane];

    int node[K_NBR];
    #pragma unroll
    for (int j = 0; j < K_NBR; j++)
        node[j] = __shfl_sync(0xffffffffu, mynode, j);

    const int d = lane * 4;

    float4 qv[K_NBR], kv[K_NBR];
    #pragma unroll
    for (int j = 0; j < K_NBR; j++) {
        const float* base = g_table + (size_t)node[j] * 384;
        qv[j] = *(const float4*)(base + d);
        kv[j] = *(const float4*)(base + 128 + d);
    }

    float scol[K_NBR];
    #pragma unroll
    for (int i = 0; i < K_NBR; i++) {
        #pragma unroll
        for (int j = 0; j < K_NBR; j++) {
            float s = qv[i].x * kv[j].x;
            s = fmaf(qv[i].y, kv[j].y, s);
            s = fmaf(qv[i].z, kv[j].z, s);
            s = fmaf(qv[i].w, kv[j].w, s);
            s += __shfl_xor_sync(0xffffffffu, s, 16);
            s += __shfl_xor_sync(0xffffffffu, s, 8);
            s += __shfl_xor_sync(0xffffffffu, s, 4);
            s += __shfl_xor_sync(0xffffffffu, s, 2);
            s += __shfl_xor_sync(0xffffffffu, s, 1);
            if (lane == j) scol[i] = s;
        }
    }

    float4 vv[K_NBR];
    #pragma unroll
    for (int j = 0; j < K_NBR; j++)
        vv[j] = *(const float4*)(g_table + (size_t)node[j] * 384 + 256 + d);

    float colw = 0.f;
    #pragma unroll
    for (int i = 0; i < K_NBR; i++) {
        float s = (lane < K_NBR) ? scol[i] : -1e30f;
        float m = s;
        m = fmaxf(m, __shfl_xor_sync(0xffffffffu, m, 16));
        m = fmaxf(m, __shfl_xor_sync(0xffffffffu, m, 8));
        m = fmaxf(m, __shfl_xor_sync(0xffffffffu, m, 4));
        m = fmaxf(m, __shfl_xor_sync(0xffffffffu, m, 2));
        m = fmaxf(m, __shfl_xor_sync(0xffffffffu, m, 1));
        float e = (lane < K_NBR) ? __expf(s - m) : 0.f;
        float sum = e;
        sum += __shfl_xor_sync(0xffffffffu, sum, 16);
        sum += __shfl_xor_sync(0xffffffffu, sum, 8);
        sum += __shfl_xor_sync(0xffffffffu, sum, 4);
        sum += __shfl_xor_sync(0xffffffffu, sum, 2);
        sum += __shfl_xor_sync(0xffffffffu, sum, 1);
        colw += e / sum;
    }

    float4 o = make_float4(0.f, 0.f, 0.f, 0.f);
    #pragma unroll
    for (int j = 0; j < K_NBR; j++) {
        float cw = __shfl_sync(0xffffffffu, colw, j);
        o.x = fmaf(cw, vv[j].x, o.x);
        o.y = fmaf(cw, vv[j].y, o.y);
        o.z = fmaf(cw, vv[j].z, o.z);
        o.w = fmaf(cw, vv[j].w, o.w);
    }
    *(float4*)(out + (size_t)b * H_DIM + d) = o;
}

// ---------------------------------------------------------------------------
extern "C" void kernel_launch(void* const* d_in, const int* in_sizes, int n_in,
                              void* d_out, int out_size) {
    const int*   neighbors = (const int*)d_in[0];
    const float* embed     = (const float*)d_in[1];
    const float* W1a       = (const float*)d_in[2];
    const float* W1b       = (const float*)d_in[3];
    const float* W2a       = (const float*)d_in[4];
    const float* W2b       = (const float*)d_in[5];
    const float* W3a       = (const float*)d_in[6];
    const float* W3b       = (const float*)d_in[7];
    float* out = (float*)d_out;

    prep_weights_kernel<<<144, 256>>>(W1a, W1b, W2a, W2b, W3a, W3b);

    cudaFuncSetAttribute(precompute_mma_kernel,
                         cudaFuncAttributeMaxDynamicSharedMemorySize,
                         (int)PC_SMEM);
    const int grid1 = (N_NODES + 127) / 128;   // 782
    precompute_mma_kernel<<<grid1, 256, PC_SMEM>>>(embed);

    attention_kernel<<<B_BATCH / 8, 256>>>(neighbors, out);
}

// round 8
// speedup vs baseline: 1.2835x; 1.0236x over previous
#include <cuda_runtime.h>
#include <cuda_fp16.h>
#include <cstdint>
#include <cstddef>

#define N_NODES 100000
#define B_BATCH 20000
#define K_NBR   10
#define F_DIM   256
#define H_DIM   128

// ---------------------------------------------------------------------------
// Device scratch
// ---------------------------------------------------------------------------
// q,k as fp16 (dot-product operands only), v as fp32 (output-linear).
__device__ __half g_qk[(size_t)N_NODES * 256];   // [node][q(128) | k(128)]
__device__ float  g_v [(size_t)N_NODES * 128];   // [node][v(128)]
// Prepacked fp16 B fragments (mma.m16n8k16 register layout), single term.
__device__ uint2 g_Ba[3 * 16 * 512];
__device__ uint2 g_Bb[3 *  8 * 512];

// ---------------------------------------------------------------------------
// Helpers
// ---------------------------------------------------------------------------
__device__ __forceinline__ uint32_t smem_u32(const void* p) {
    uint32_t a;
    asm("{ .reg .u64 t; cvta.to.shared.u64 t, %1; cvt.u32.u64 %0, t; }"
        : "=r"(a) : "l"(p));
    return a;
}
__device__ __forceinline__ uint32_t pack_f16x2(float a, float b) {
    half2 h = __floats2half2_rn(a, b);
    return *(uint32_t*)&h;
}
__device__ __forceinline__ float tanh_fast(float x) {
    float e = __expf(2.f * x);
    return 1.f - __fdividef(2.f, e + 1.f);
}
__device__ __forceinline__ void ldm4(uint32_t* r, uint32_t addr) {
    asm volatile("ldmatrix.sync.aligned.m8n8.x4.shared.b16 {%0,%1,%2,%3}, [%4];"
                 : "=r"(r[0]), "=r"(r[1]), "=r"(r[2]), "=r"(r[3]) : "r"(addr));
}
__device__ __forceinline__ void mma16816(float* d, const uint32_t* a,
                                         uint32_t b0, uint32_t b1) {
    asm volatile(
        "mma.sync.aligned.m16n8k16.row.col.f32.f16.f16.f32 "
        "{%0,%1,%2,%3}, {%4,%5,%6,%7}, {%8,%9}, {%0,%1,%2,%3};"
        : "+f"(d[0]), "+f"(d[1]), "+f"(d[2]), "+f"(d[3])
        : "r"(a[0]), "r"(a[1]), "r"(a[2]), "r"(a[3]), "r"(b0), "r"(b1));
}

// ---------------------------------------------------------------------------
// Kernel 0: prepack weights into mma B-fragment layout (fp16, single term).
// ---------------------------------------------------------------------------
__global__ void prep_weights_kernel(
    const float* __restrict__ W1a, const float* __restrict__ W1b,
    const float* __restrict__ W2a, const float* __restrict__ W2b,
    const float* __restrict__ W3a, const float* __restrict__ W3b)
{
    const float* Wa[3] = {W1a, W2a, W3a};
    const float* Wb[3] = {W1b, W2b, W3b};
    int i = blockIdx.x * blockDim.x + threadIdx.x;   // 36864 threads
    const float* W;
    uint2* dst;
    int lane, nt, ks;
    if (i < 24576) {                                 // Ba: 3*16*16*32
        lane = i & 31; nt = (i >> 5) & 15; ks = (i >> 9) & 15;
        int p = i >> 13;
        W = Wa[p];
        dst = g_Ba + (size_t)(p * 16 + ks) * 512 + nt * 32 + lane;
    } else {                                         // Bb: 3*8*16*32
        int ib = i - 24576;
        lane = ib & 31; nt = (ib >> 5) & 15; ks = (ib >> 9) & 7;
        int p = ib >> 12;
        W = Wb[p];
        dst = g_Bb + (size_t)(p * 8 + ks) * 512 + nt * 32 + lane;
    }
    int k = ks * 16 + (lane & 3) * 2;
    int n = nt * 8 + (lane >> 2);
    float w00 = W[(size_t)k * H_DIM + n];
    float w01 = W[(size_t)(k + 1) * H_DIM + n];
    float w10 = W[(size_t)(k + 8) * H_DIM + n];
    float w11 = W[(size_t)(k + 9) * H_DIM + n];
    uint2 fr;
    fr.x = pack_f16x2(w00, w01);
    fr.y = pack_f16x2(w10, w11);
    *dst = fr;
}

// ---------------------------------------------------------------------------
// Kernel 1: HMMA precompute. CTA = 128x128 tile, 8 warps as 2m x 4n,
// warp tile 64x32. Single-pass fp16, fp32 accum, B fragments prefetched
// one k-step ahead (software pipeline).
// ---------------------------------------------------------------------------
#define XSTR 264
#define HSTR 136
#define X_OFF 0u
#define H_OFF 67584u                     // 128*264*2
#define PC_SMEM 102400u

__global__ void __launch_bounds__(256, 2) precompute_mma_kernel(
    const float* __restrict__ embed)
{
    extern __shared__ unsigned char smem[];
    const uint32_t sbase = smem_u32(smem);
    const int tid  = threadIdx.x;
    const int wid  = tid >> 5;
    const int lane = tid & 31;
    const int wm   = wid & 1;
    const int wn   = wid >> 1;
    const long brow = (long)blockIdx.x * 128;

    const uint32_t loffX = (uint32_t)((lane & 15) * XSTR + (lane >> 4) * 8) * 2;
    const uint32_t loffH = (uint32_t)((lane & 15) * HSTR + (lane >> 4) * 8) * 2;

    for (int i = tid; i < 128 * 64; i += 256) {
        int r  = i >> 6;
        int c4 = i & 63;
        long grow = brow + r;
        float4 v = make_float4(0.f, 0.f, 0.f, 0.f);
        if (grow < N_NODES) v = *(const float4*)(embed + grow * F_DIM + c4 * 4);
        uint32_t off = ((uint32_t)r * XSTR + c4 * 4) * 2;
        *(uint32_t*)(smem + X_OFF + off)     = pack_f16x2(v.x, v.y);
        *(uint32_t*)(smem + X_OFF + off + 4) = pack_f16x2(v.z, v.w);
    }
    __syncthreads();

    const int rbase = (lane >> 2);
    const int cbase = (lane & 3) * 2;

    for (int p = 0; p < 3; p++) {
        float acc[4][4][4];
        #pragma unroll
        for (int mt = 0; mt < 4; mt++)
            #pragma unroll
            for (int nt = 0; nt < 4; nt++)
                #pragma unroll
                for (int c = 0; c < 4; c++) acc[mt][nt][c] = 0.f;

        // ================= GEMM1: X[128,256] @ Wa -> 128x128 =================
        {
            const uint2* pb = g_Ba + (size_t)(p * 16) * 512 + (wn * 4) * 32 + lane;
            uint2 bf[4], bn[4];
            #pragma unroll
            for (int j = 0; j < 4; j++) bf[j] = pb[j * 32];
            for (int ks = 0; ks < 16; ks++) {
                const uint2* np = pb + (ks + 1) * 512;
                #pragma unroll
                for (int j = 0; j < 4; j++)
                    bn[j] = (ks < 15) ? np[j * 32] : make_uint2(0u, 0u);
                uint32_t a[4][4];
                uint32_t kb = (uint32_t)ks * 32;
                #pragma unroll
                for (int mt = 0; mt < 4; mt++) {
                    uint32_t ro = (uint32_t)(wm * 64 + mt * 16) * XSTR * 2;
                    ldm4(a[mt], sbase + X_OFF + ro + kb + loffX);
                }
                #pragma unroll
                for (int j = 0; j < 4; j++) {
                    #pragma unroll
                    for (int mt = 0; mt < 4; mt++)
                        mma16816(acc[mt][j], a[mt], bf[j].x, bf[j].y);
                }
                #pragma unroll
                for (int j = 0; j < 4; j++) bf[j] = bn[j];
            }
        }

        // ---- Epilogue 1: tanh -> H smem (fp16) ----
        #pragma unroll
        for (int mt = 0; mt < 4; mt++) {
            #pragma unroll
            for (int nt = 0; nt < 4; nt++) {
                int col = wn * 32 + nt * 8 + cbase;
                int r0  = wm * 64 + mt * 16 + rbase;
                float t0 = tanh_fast(acc[mt][nt][0]);
                float t1 = tanh_fast(acc[mt][nt][1]);
                float t2 = tanh_fast(acc[mt][nt][2]);
                float t3 = tanh_fast(acc[mt][nt][3]);
                uint32_t o0 = ((uint32_t)r0 * HSTR + col) * 2;
                uint32_t o1 = ((uint32_t)(r0 + 8) * HSTR + col) * 2;
                *(uint32_t*)(smem + H_OFF + o0) = pack_f16x2(t0, t1);
                *(uint32_t*)(smem + H_OFF + o1) = pack_f16x2(t2, t3);
            }
        }
        __syncthreads();

        // ================= GEMM2: H[128,128] @ Wb -> 128x128 =================
        #pragma unroll
        for (int mt = 0; mt < 4; mt++)
            #pragma unroll
            for (int nt = 0; nt < 4; nt++)
                #pragma unroll
                for (int c = 0; c < 4; c++) acc[mt][nt][c] = 0.f;

        {
            const uint2* pb = g_Bb + (size_t)(p * 8) * 512 + (wn * 4) * 32 + lane;
            uint2 bf[4], bn[4];
            #pragma unroll
            for (int j = 0; j < 4; j++) bf[j] = pb[j * 32];
            for (int ks = 0; ks < 8; ks++) {
                const uint2* np = pb + (ks + 1) * 512;
                #pragma unroll
                for (int j = 0; j < 4; j++)
                    bn[j] = (ks < 7) ? np[j * 32] : make_uint2(0u, 0u);
                uint32_t a[4][4];
                uint32_t kb = (uint32_t)ks * 32;
                #pragma unroll
                for (int mt = 0; mt < 4; mt++) {
                    uint32_t ro = (uint32_t)(wm * 64 + mt * 16) * HSTR * 2;
                    ldm4(a[mt], sbase + H_OFF + ro + kb + loffH);
                }
                #pragma unroll
                for (int j = 0; j < 4; j++) {
                    #pragma unroll
                    for (int mt = 0; mt < 4; mt++)
                        mma16816(acc[mt][j], a[mt], bf[j].x, bf[j].y);
                }
                #pragma unroll
                for (int j = 0; j < 4; j++) bf[j] = bn[j];
            }
        }

        // ---- Epilogue 2: write q,k (fp16) or v (fp32) ----
        #pragma unroll
        for (int mt = 0; mt < 4; mt++) {
            #pragma unroll
            for (int nt = 0; nt < 4; nt++) {
                int col = wn * 32 + nt * 8 + cbase;
                long r0 = brow + wm * 64 + mt * 16 + rbase;
                if (p < 2) {
                    if (r0 < N_NODES)
                        *(uint32_t*)(g_qk + r0 * 256 + p * 128 + col) =
                            pack_f16x2(acc[mt][nt][0], acc[mt][nt][1]);
                    if (r0 + 8 < N_NODES)
                        *(uint32_t*)(g_qk + (r0 + 8) * 256 + p * 128 + col) =
                            pack_f16x2(acc[mt][nt][2], acc[mt][nt][3]);
                } else {
                    if (r0 < N_NODES)
                        *(float2*)(g_v + r0 * 128 + col) =
                            make_float2(acc[mt][nt][0], acc[mt][nt][1]);
                    if (r0 + 8 < N_NODES)
                        *(float2*)(g_v + (r0 + 8) * 128 + col) =
                            make_float2(acc[mt][nt][2], acc[mt][nt][3]);
                }
            }
        }
        __syncthreads();
    }
}

// ---------------------------------------------------------------------------
// Kernel 2: warp-autonomous attention. q,k gathered as fp16 (8B/lane/row),
// v as fp32. Scores/softmax via shfl butterflies, no shared memory.
// ---------------------------------------------------------------------------
__global__ void __launch_bounds__(256) attention_kernel(
    const int* __restrict__ neighbors, float* __restrict__ out)
{
    const int b    = blockIdx.x * 8 + (threadIdx.x >> 5);
    const int lane = threadIdx.x & 31;

    int mynode = 0;
    if (lane < K_NBR) mynode = neighbors[(size_t)b * K_NBR + lane];

    int node[K_NBR];
    #pragma unroll
    for (int j = 0; j < K_NBR; j++)
        node[j] = __shfl_sync(0xffffffffu, mynode, j);

    const int d = lane * 4;

    // Gather q,k rows (fp16, one uint2 = 4 halves per lane per row)
    float4 qv[K_NBR], kv[K_NBR];
    #pragma unroll
    for (int j = 0; j < K_NBR; j++) {
        const __half* base = g_qk + (size_t)node[j] * 256;
        uint2 qr = *(const uint2*)(base + d);
        uint2 kr = *(const uint2*)(base + 128 + d);
        float2 q0 = __half22float2(*(half2*)&qr.x);
        float2 q1 = __half22float2(*(half2*)&qr.y);
        float2 k0 = __half22float2(*(half2*)&kr.x);
        float2 k1 = __half22float2(*(half2*)&kr.y);
        qv[j] = make_float4(q0.x, q0.y, q1.x, q1.y);
        kv[j] = make_float4(k0.x, k0.y, k1.x, k1.y);
    }

    // Score matrix: lane j retains s[i][j] in scol[i]
    float scol[K_NBR];
    #pragma unroll
    for (int i = 0; i < K_NBR; i++) {
        #pragma unroll
        for (int j = 0; j < K_NBR; j++) {
            float s = qv[i].x * kv[j].x;
            s = fmaf(qv[i].y, kv[j].y, s);
            s = fmaf(qv[i].z, kv[j].z, s);
            s = fmaf(qv[i].w, kv[j].w, s);
            s += __shfl_xor_sync(0xffffffffu, s, 16);
            s += __shfl_xor_sync(0xffffffffu, s, 8);
            s += __shfl_xor_sync(0xffffffffu, s, 4);
            s += __shfl_xor_sync(0xffffffffu, s, 2);
            s += __shfl_xor_sync(0xffffffffu, s, 1);
            if (lane == j) scol[i] = s;
        }
    }

    // Prefetch v rows (fp32)
    float4 vv[K_NBR];
    #pragma unroll
    for (int j = 0; j < K_NBR; j++)
        vv[j] = *(const float4*)(g_v + (size_t)node[j] * 128 + d);

    // Softmax + column weights
    float colw = 0.f;
    #pragma unroll
    for (int i = 0; i < K_NBR; i++) {
        float s = (lane < K_NBR) ? scol[i] : -1e30f;
        float m = s;
        m = fmaxf(m, __shfl_xor_sync(0xffffffffu, m, 16));
        m = fmaxf(m, __shfl_xor_sync(0xffffffffu, m, 8));
        m = fmaxf(m, __shfl_xor_sync(0xffffffffu, m, 4));
        m = fmaxf(m, __shfl_xor_sync(0xffffffffu, m, 2));
        m = fmaxf(m, __shfl_xor_sync(0xffffffffu, m, 1));
        float e = (lane < K_NBR) ? __expf(s - m) : 0.f;
        float sum = e;
        sum += __shfl_xor_sync(0xffffffffu, sum, 16);
        sum += __shfl_xor_sync(0xffffffffu, sum, 8);
        sum += __shfl_xor_sync(0xffffffffu, sum, 4);
        sum += __shfl_xor_sync(0xffffffffu, sum, 2);
        sum += __shfl_xor_sync(0xffffffffu, sum, 1);
        colw += e / sum;
    }

    // out[b, 4l..4l+3] = sum_j colw_j * v_j
    float4 o = make_float4(0.f, 0.f, 0.f, 0.f);
    #pragma unroll
    for (int j = 0; j < K_NBR; j++) {
        float cw = __shfl_sync(0xffffffffu, colw, j);
        o.x = fmaf(cw, vv[j].x, o.x);
        o.y = fmaf(cw, vv[j].y, o.y);
        o.z = fmaf(cw, vv[j].z, o.z);
        o.w = fmaf(cw, vv[j].w, o.w);
    }
    *(float4*)(out + (size_t)b * H_DIM + d) = o;
}

// ---------------------------------------------------------------------------
extern "C" void kernel_launch(void* const* d_in, const int* in_sizes, int n_in,
                              void* d_out, int out_size) {
    const int*   neighbors = (const int*)d_in[0];
    const float* embed     = (const float*)d_in[1];
    const float* W1a       = (const float*)d_in[2];
    const float* W1b       = (const float*)d_in[3];
    const float* W2a       = (const float*)d_in[4];
    const float* W2b       = (const float*)d_in[5];
    const float* W3a       = (const float*)d_in[6];
    const float* W3b       = (const float*)d_in[7];
    float* out = (float*)d_out;

    prep_weights_kernel<<<144, 256>>>(W1a, W1b, W2a, W2b, W3a, W3b);

    cudaFuncSetAttribute(precompute_mma_kernel,
                         cudaFuncAttributeMaxDynamicSharedMemorySize,
                         (int)PC_SMEM);
    const int grid1 = (N_NODES + 127) / 128;   // 782
    precompute_mma_kernel<<<grid1, 256, PC_SMEM>>>(embed);

    attention_kernel<<<B_BATCH / 8, 256>>>(neighbors, out);
}

// round 9
// speedup vs baseline: 1.3107x; 1.0212x over previous
#include <cuda_runtime.h>
#include <cuda_fp16.h>
#include <cstdint>
#include <cstddef>

#define N_NODES 100000
#define B_BATCH 20000
#define K_NBR   10
#define F_DIM   256
#define H_DIM   128

// ---------------------------------------------------------------------------
// Device scratch
// ---------------------------------------------------------------------------
__device__ __half g_qk[(size_t)N_NODES * 256];   // [node][q(128) | k(128)]
__device__ float  g_v [(size_t)N_NODES * 128];   // [node][v(128)]
__device__ uint2 g_Ba[3 * 16 * 512];             // fp16 B fragments, GEMM1
__device__ uint2 g_Bb[3 *  8 * 512];             // fp16 B fragments, GEMM2

// ---------------------------------------------------------------------------
// Helpers
// ---------------------------------------------------------------------------
__device__ __forceinline__ uint32_t smem_u32(const void* p) {
    uint32_t a;
    asm("{ .reg .u64 t; cvta.to.shared.u64 t, %1; cvt.u32.u64 %0, t; }"
        : "=r"(a) : "l"(p));
    return a;
}
__device__ __forceinline__ uint32_t pack_f16x2(float a, float b) {
    half2 h = __floats2half2_rn(a, b);
    return *(uint32_t*)&h;
}
__device__ __forceinline__ float tanh_fast(float x) {
    float y;
    asm("tanh.approx.f32 %0, %1;" : "=f"(y) : "f"(x));
    return y;
}
__device__ __forceinline__ void ldm4(uint32_t* r, uint32_t addr) {
    asm volatile("ldmatrix.sync.aligned.m8n8.x4.shared.b16 {%0,%1,%2,%3}, [%4];"
                 : "=r"(r[0]), "=r"(r[1]), "=r"(r[2]), "=r"(r[3]) : "r"(addr));
}
__device__ __forceinline__ void mma16816(float* d, const uint32_t* a,
                                         uint32_t b0, uint32_t b1) {
    asm volatile(
        "mma.sync.aligned.m16n8k16.row.col.f32.f16.f16.f32 "
        "{%0,%1,%2,%3}, {%4,%5,%6,%7}, {%8,%9}, {%0,%1,%2,%3};"
        : "+f"(d[0]), "+f"(d[1]), "+f"(d[2]), "+f"(d[3])
        : "r"(a[0]), "r"(a[1]), "r"(a[2]), "r"(a[3]), "r"(b0), "r"(b1));
}

// ---------------------------------------------------------------------------
// Kernel 0: prepack weights into mma B-fragment layout (fp16, single term).
// One block per (matrix,p,kstep): coalesced 16x128 tile load -> smem ->
// fragment scatter. Grid 72, block 128.
// ---------------------------------------------------------------------------
__global__ void prep_weights_kernel(
    const float* __restrict__ W1a, const float* __restrict__ W1b,
    const float* __restrict__ W2a, const float* __restrict__ W2b,
    const float* __restrict__ W3a, const float* __restrict__ W3b)
{
    __shared__ float st[16][132];                 // padded vs bank conflicts
    const float* Wa[3] = {W1a, W2a, W3a};
    const float* Wb[3] = {W1b, W2b, W3b};

    const int bx  = blockIdx.x;
    const int tid = threadIdx.x;
    const float* W;
    uint2* dstbase;
    int ks;
    if (bx < 48) {                                // Ba: p(3) x ks(16)
        int p = bx >> 4; ks = bx & 15;
        W = Wa[p];
        dstbase = g_Ba + (size_t)(p * 16 + ks) * 512;
    } else {                                      // Bb: p(3) x ks(8)
        int i = bx - 48;
        int p = i >> 3; ks = i & 7;
        W = Wb[p];
        dstbase = g_Bb + (size_t)(p * 8 + ks) * 512;
    }

    // Coalesced load of W[ks*16 .. +15][0..127]
    const float* src = W + (size_t)ks * 16 * H_DIM;
    for (int i = tid; i < 16 * 32; i += 128) {    // float4 granularity
        int r  = i >> 5;
        int c4 = i & 31;
        float4 v = *(const float4*)(src + r * H_DIM + c4 * 4);
        st[r][c4 * 4 + 0] = v.x;
        st[r][c4 * 4 + 1] = v.y;
        st[r][c4 * 4 + 2] = v.z;
        st[r][c4 * 4 + 3] = v.w;
    }
    __syncthreads();

    // 512 fragment entries; each thread writes 4
    for (int e = tid; e < 512; e += 128) {
        int nt   = e >> 5;
        int lane = e & 31;
        int kl   = (lane & 3) * 2;
        int n    = nt * 8 + (lane >> 2);
        uint2 fr;
        fr.x = pack_f16x2(st[kl][n],     st[kl + 1][n]);
        fr.y = pack_f16x2(st[kl + 8][n], st[kl + 9][n]);
        dstbase[e] = fr;
    }
}

// ---------------------------------------------------------------------------
// Kernel 1: HMMA precompute. CTA = 128x128 tile, 8 warps as 2m x 4n,
// warp tile 64x32. Single-pass fp16, fp32 accum, B prefetched 1 kstep ahead.
// ---------------------------------------------------------------------------
#define XSTR 264
#define HSTR 136
#define X_OFF 0u
#define H_OFF 67584u                     // 128*264*2
#define PC_SMEM 102400u

__global__ void __launch_bounds__(256, 2) precompute_mma_kernel(
    const float* __restrict__ embed)
{
    extern __shared__ unsigned char smem[];
    const uint32_t sbase = smem_u32(smem);
    const int tid  = threadIdx.x;
    const int wid  = tid >> 5;
    const int lane = tid & 31;
    const int wm   = wid & 1;
    const int wn   = wid >> 1;
    const long brow = (long)blockIdx.x * 128;

    const uint32_t loffX = (uint32_t)((lane & 15) * XSTR + (lane >> 4) * 8) * 2;
    const uint32_t loffH = (uint32_t)((lane & 15) * HSTR + (lane >> 4) * 8) * 2;

    for (int i = tid; i < 128 * 64; i += 256) {
        int r  = i >> 6;
        int c4 = i & 63;
        long grow = brow + r;
        float4 v = make_float4(0.f, 0.f, 0.f, 0.f);
        if (grow < N_NODES) v = *(const float4*)(embed + grow * F_DIM + c4 * 4);
        uint32_t off = ((uint32_t)r * XSTR + c4 * 4) * 2;
        *(uint32_t*)(smem + X_OFF + off)     = pack_f16x2(v.x, v.y);
        *(uint32_t*)(smem + X_OFF + off + 4) = pack_f16x2(v.z, v.w);
    }
    __syncthreads();

    const int rbase = (lane >> 2);
    const int cbase = (lane & 3) * 2;

    for (int p = 0; p < 3; p++) {
        float acc[4][4][4];
        #pragma unroll
        for (int mt = 0; mt < 4; mt++)
            #pragma unroll
            for (int nt = 0; nt < 4; nt++)
                #pragma unroll
                for (int c = 0; c < 4; c++) acc[mt][nt][c] = 0.f;

        // ================= GEMM1: X[128,256] @ Wa -> 128x128 =================
        {
            const uint2* pb = g_Ba + (size_t)(p * 16) * 512 + (wn * 4) * 32 + lane;
            uint2 bf[4], bn[4];
            #pragma unroll
            for (int j = 0; j < 4; j++) bf[j] = pb[j * 32];
            for (int ks = 0; ks < 16; ks++) {
                const uint2* np = pb + (ks + 1) * 512;
                #pragma unroll
                for (int j = 0; j < 4; j++)
                    bn[j] = (ks < 15) ? np[j * 32] : make_uint2(0u, 0u);
                uint32_t a[4][4];
                uint32_t kb = (uint32_t)ks * 32;
                #pragma unroll
                for (int mt = 0; mt < 4; mt++) {
                    uint32_t ro = (uint32_t)(wm * 64 + mt * 16) * XSTR * 2;
                    ldm4(a[mt], sbase + X_OFF + ro + kb + loffX);
                }
                #pragma unroll
                for (int j = 0; j < 4; j++) {
                    #pragma unroll
                    for (int mt = 0; mt < 4; mt++)
                        mma16816(acc[mt][j], a[mt], bf[j].x, bf[j].y);
                }
                #pragma unroll
                for (int j = 0; j < 4; j++) bf[j] = bn[j];
            }
        }

        // ---- Epilogue 1: tanh.approx -> H smem (fp16) ----
        #pragma unroll
        for (int mt = 0; mt < 4; mt++) {
            #pragma unroll
            for (int nt = 0; nt < 4; nt++) {
                int col = wn * 32 + nt * 8 + cbase;
                int r0  = wm * 64 + mt * 16 + rbase;
                float t0 = tanh_fast(acc[mt][nt][0]);
                float t1 = tanh_fast(acc[mt][nt][1]);
                float t2 = tanh_fast(acc[mt][nt][2]);
                float t3 = tanh_fast(acc[mt][nt][3]);
                uint32_t o0 = ((uint32_t)r0 * HSTR + col) * 2;
                uint32_t o1 = ((uint32_t)(r0 + 8) * HSTR + col) * 2;
                *(uint32_t*)(smem + H_OFF + o0) = pack_f16x2(t0, t1);
                *(uint32_t*)(smem + H_OFF + o1) = pack_f16x2(t2, t3);
            }
        }
        __syncthreads();

        // ================= GEMM2: H[128,128] @ Wb -> 128x128 =================
        #pragma unroll
        for (int mt = 0; mt < 4; mt++)
            #pragma unroll
            for (int nt = 0; nt < 4; nt++)
                #pragma unroll
                for (int c = 0; c < 4; c++) acc[mt][nt][c] = 0.f;

        {
            const uint2* pb = g_Bb + (size_t)(p * 8) * 512 + (wn * 4) * 32 + lane;
            uint2 bf[4], bn[4];
            #pragma unroll
            for (int j = 0; j < 4; j++) bf[j] = pb[j * 32];
            for (int ks = 0; ks < 8; ks++) {
                const uint2* np = pb + (ks + 1) * 512;
                #pragma unroll
                for (int j = 0; j < 4; j++)
                    bn[j] = (ks < 7) ? np[j * 32] : make_uint2(0u, 0u);
                uint32_t a[4][4];
                uint32_t kb = (uint32_t)ks * 32;
                #pragma unroll
                for (int mt = 0; mt < 4; mt++) {
                    uint32_t ro = (uint32_t)(wm * 64 + mt * 16) * HSTR * 2;
                    ldm4(a[mt], sbase + H_OFF + ro + kb + loffH);
                }
                #pragma unroll
                for (int j = 0; j < 4; j++) {
                    #pragma unroll
                    for (int mt = 0; mt < 4; mt++)
                        mma16816(acc[mt][j], a[mt], bf[j].x, bf[j].y);
                }
                #pragma unroll
                for (int j = 0; j < 4; j++) bf[j] = bn[j];
            }
        }

        // ---- Epilogue 2: write q,k (fp16) or v (fp32) ----
        #pragma unroll
        for (int mt = 0; mt < 4; mt++) {
            #pragma unroll
            for (int nt = 0; nt < 4; nt++) {
                int col = wn * 32 + nt * 8 + cbase;
                long r0 = brow + wm * 64 + mt * 16 + rbase;
                if (p < 2) {
                    if (r0 < N_NODES)
                        *(uint32_t*)(g_qk + r0 * 256 + p * 128 + col) =
                            pack_f16x2(acc[mt][nt][0], acc[mt][nt][1]);
                    if (r0 + 8 < N_NODES)
                        *(uint32_t*)(g_qk + (r0 + 8) * 256 + p * 128 + col) =
                            pack_f16x2(acc[mt][nt][2], acc[mt][nt][3]);
                } else {
                    if (r0 < N_NODES)
                        *(float2*)(g_v + r0 * 128 + col) =
                            make_float2(acc[mt][nt][0], acc[mt][nt][1]);
                    if (r0 + 8 < N_NODES)
                        *(float2*)(g_v + (r0 + 8) * 128 + col) =
                            make_float2(acc[mt][nt][2], acc[mt][nt][3]);
                }
            }
        }
        __syncthreads();
    }
}

// ---------------------------------------------------------------------------
// Kernel 2: warp-autonomous attention (unchanged from round 8).
// ---------------------------------------------------------------------------
__global__ void __launch_bounds__(256) attention_kernel(
    const int* __restrict__ neighbors, float* __restrict__ out)
{
    const int b    = blockIdx.x * 8 + (threadIdx.x >> 5);
    const int lane = threadIdx.x & 31;

    int mynode = 0;
    if (lane < K_NBR) mynode = neighbors[(size_t)b * K_NBR + lane];

    int node[K_NBR];
    #pragma unroll
    for (int j = 0; j < K_NBR; j++)
        node[j] = __shfl_sync(0xffffffffu, mynode, j);

    const int d = lane * 4;

    float4 qv[K_NBR], kv[K_NBR];
    #pragma unroll
    for (int j = 0; j < K_NBR; j++) {
        const __half* base = g_qk + (size_t)node[j] * 256;
        uint2 qr = *(const uint2*)(base + d);
        uint2 kr = *(const uint2*)(base + 128 + d);
        float2 q0 = __half22float2(*(half2*)&qr.x);
        float2 q1 = __half22float2(*(half2*)&qr.y);
        float2 k0 = __half22float2(*(half2*)&kr.x);
        float2 k1 = __half22float2(*(half2*)&kr.y);
        qv[j] = make_float4(q0.x, q0.y, q1.x, q1.y);
        kv[j] = make_float4(k0.x, k0.y, k1.x, k1.y);
    }

    float scol[K_NBR];
    #pragma unroll
    for (int i = 0; i < K_NBR; i++) {
        #pragma unroll
        for (int j = 0; j < K_NBR; j++) {
            float s = qv[i].x * kv[j].x;
            s = fmaf(qv[i].y, kv[j].y, s);
            s = fmaf(qv[i].z, kv[j].z, s);
            s = fmaf(qv[i].w, kv[j].w, s);
            s += __shfl_xor_sync(0xffffffffu, s, 16);
            s += __shfl_xor_sync(0xffffffffu, s, 8);
            s += __shfl_xor_sync(0xffffffffu, s, 4);
            s += __shfl_xor_sync(0xffffffffu, s, 2);
            s += __shfl_xor_sync(0xffffffffu, s, 1);
            if (lane == j) scol[i] = s;
        }
    }

    float4 vv[K_NBR];
    #pragma unroll
    for (int j = 0; j < K_NBR; j++)
        vv[j] = *(const float4*)(g_v + (size_t)node[j] * 128 + d);

    float colw = 0.f;
    #pragma unroll
    for (int i = 0; i < K_NBR; i++) {
        float s = (lane < K_NBR) ? scol[i] : -1e30f;
        float m = s;
        m = fmaxf(m, __shfl_xor_sync(0xffffffffu, m, 16));
        m = fmaxf(m, __shfl_xor_sync(0xffffffffu, m, 8));
        m = fmaxf(m, __shfl_xor_sync(0xffffffffu, m, 4));
        m = fmaxf(m, __shfl_xor_sync(0xffffffffu, m, 2));
        m = fmaxf(m, __shfl_xor_sync(0xffffffffu, m, 1));
        float e = (lane < K_NBR) ? __expf(s - m) : 0.f;
        float sum = e;
        sum += __shfl_xor_sync(0xffffffffu, sum, 16);
        sum += __shfl_xor_sync(0xffffffffu, sum, 8);
        sum += __shfl_xor_sync(0xffffffffu, sum, 4);
        sum += __shfl_xor_sync(0xffffffffu, sum, 2);
        sum += __shfl_xor_sync(0xffffffffu, sum, 1);
        colw += e / sum;
    }

    float4 o = make_float4(0.f, 0.f, 0.f, 0.f);
    #pragma unroll
    for (int j = 0; j < K_NBR; j++) {
        float cw = __shfl_sync(0xffffffffu, colw, j);
        o.x = fmaf(cw, vv[j].x, o.x);
        o.y = fmaf(cw, vv[j].y, o.y);
        o.z = fmaf(cw, vv[j].z, o.z);
        o.w = fmaf(cw, vv[j].w, o.w);
    }
    *(float4*)(out + (size_t)b * H_DIM + d) = o;
}

// ---------------------------------------------------------------------------
extern "C" void kernel_launch(void* const* d_in, const int* in_sizes, int n_in,
                              void* d_out, int out_size) {
    const int*   neighbors = (const int*)d_in[0];
    const float* embed     = (const float*)d_in[1];
    const float* W1a       = (const float*)d_in[2];
    const float* W1b       = (const float*)d_in[3];
    const float* W2a       = (const float*)d_in[4];
    const float* W2b       = (const float*)d_in[5];
    const float* W3a       = (const float*)d_in[6];
    const float* W3b       = (const float*)d_in[7];
    float* out = (float*)d_out;

    prep_weights_kernel<<<72, 128>>>(W1a, W1b, W2a, W2b, W3a, W3b);

    cudaFuncSetAttribute(precompute_mma_kernel,
                         cudaFuncAttributeMaxDynamicSharedMemorySize,
                         (int)PC_SMEM);
    const int grid1 = (N_NODES + 127) / 128;   // 782
    precompute_mma_kernel<<<grid1, 256, PC_SMEM>>>(embed);

    attention_kernel<<<B_BATCH / 8, 256>>>(neighbors, out);
}